// round 6
// baseline (speedup 1.0000x reference)
#include <cuda_runtime.h>
#include <math.h>

// ---------------- problem constants ----------------
#define S_NUM   16
#define O_NUM   15
#define BATCH   4096
#define N_IN    64
#define WSHAPE  3120
#define BSHAPE  41
#define TOTAL_ELEMS (S_NUM * BATCH * O_NUM)   // 983040
#define E_JOINT 41
#define SO_NUM  (S_NUM * O_NUM)               // 240
#define NTHR    128
#define BTILE   256                           // 128 batch-pairs per CTA
#define NBLK_B  (BATCH / BTILE)               // 16
#define NPART   (SO_NUM * NBLK_B)             // 3840
#define NPAIR   (BATCH / 2)                   // 2048
#define EPSF    1e-20f
#define TEMP    0.03f

typedef unsigned long long u64;

// scratch (allocation-free rule: __device__ globals)
__device__ float g_constw[SO_NUM * WSHAPE];   // ~3 MB
__device__ float g_obsT[N_IN * BATCH];        // 1 MB transposed obs
__device__ float g_partials[NPART];

// e-joint -> (weight seg base, inall, e offset)
__constant__ int EJ_WG[E_JOINT] = {
    0,0,0,0,0,0,  384,384,384,384,384,384,
    786,786,786,786,786,786,786,786,
    1346,1346,1346,1346,1346,1346,1346,1346,
    1970,1970,1970,1970,1970,1970,  2486,2486,2486,2486,2486,2486,  3026 };
__constant__ int EJ_IN[E_JOINT] = {
    6,6,6,6,6,6, 6,6,6,6,6,6, 8,8,8,8,8,8,8,8, 8,8,8,8,8,8,8,8,
    6,6,6,6,6,6, 6,6,6,6,6,6, 1 };
__constant__ int EJ_EB[E_JOINT] = {
    0,1,2,3,4,5, 0,1,2,3,4,5, 0,1,2,3,4,5,6,7, 0,1,2,3,4,5,6,7,
    0,1,2,3,4,5, 0,1,2,3,4,5, 0 };

// ---------------- packed f32x2 helpers ----------------
__device__ __forceinline__ u64 pk(float lo, float hi) {
    u64 r; asm("mov.b64 %0, {%1, %2};" : "=l"(r) : "f"(lo), "f"(hi)); return r;
}
__device__ __forceinline__ float2 unpk(u64 v) {
    float2 f; asm("mov.b64 {%0, %1}, %2;" : "=f"(f.x), "=f"(f.y) : "l"(v)); return f;
}
__device__ __forceinline__ u64 dup2(float x) { return pk(x, x); }
__device__ __forceinline__ u64 ffma2(u64 a, u64 b, u64 c) {
    u64 d; asm("fma.rn.f32x2 %0, %1, %2, %3;" : "=l"(d) : "l"(a), "l"(b), "l"(c));
    return d;
}

// ---------------- phase 1: gate -> constw (PRECISE: threshold-sensitive) ----
__global__ void eql_constw(const float* __restrict__ scores,
                           const float* __restrict__ base,
                           const float* __restrict__ u0,
                           const float* __restrict__ u1) {
    int i = blockIdx.x * 256 + threadIdx.x;
    if (i >= SO_NUM * WSHAPE) return;
    int ow = i % (O_NUM * WSHAPE);
    float sc    = scores[ow];
    float cs    = 1.0f / (1.0f + expf(-sc));
    float logit = logf(cs + EPSF) - logf(1.0f - cs + EPSF);
    float noise = -logf(logf(u0[i] + EPSF) / logf(u1[i] + EPSF) + EPSF);
    float z     = (logit + noise) * TEMP;
    float soft  = 1.0f / (1.0f + expf(-z));
    float hard  = (soft > 0.5f) ? 1.0f : 0.0f;
    g_constw[i] = base[ow] * ((hard - soft) + soft);
}

// ---------------- phase 1b: obs transpose (tiled, coalesced) ----------------
__global__ void eql_transpose(const float* __restrict__ obs) {
    __shared__ float tile[32][33];
    int bx = blockIdx.x * 32;   // batch base
    int dx = blockIdx.y * 32;   // dim base
    int tx = threadIdx.x, ty = threadIdx.y;  // (32, 8)
    #pragma unroll
    for (int j = 0; j < 32; j += 8)
        tile[ty + j][tx] = obs[(size_t)(bx + ty + j) * N_IN + dx + tx];
    __syncthreads();
    #pragma unroll
    for (int j = 0; j < 32; j += 8)
        g_obsT[(size_t)(dx + ty + j) * BATCH + bx + tx] = tile[tx][ty + j];
}

// ---------------- dummy launch (slot ncu capture onto eql_main = #4) -------
__global__ void eql_zero(void) {
    int i = blockIdx.x * 256 + threadIdx.x;
    if (i < NPART) g_partials[i] = 0.0f;
}

// ---------------- scalar ops (fast intrinsics; validated rel_err 3.8e-5) ---
__device__ __forceinline__ float op_mul(float a, float b, float& r) {
    r += fmaxf(-100.0f - a, 0.0f) + fmaxf(a - 100.0f, 0.0f)
       + fmaxf(-100.0f - b, 0.0f) + fmaxf(b - 100.0f, 0.0f);
    return fminf(fmaxf(a, -100.0f), 100.0f) * fminf(fmaxf(b, -100.0f), 100.0f);
}
__device__ __forceinline__ float op_div(float a, float b, float& r) {
    r += fmaxf(0.01f - b, 0.0f);
    return (b < 0.01f) ? 0.0f : __fdividef(a, b);
}
__device__ __forceinline__ float op_log(float a, float& r) {
    r += fmaxf(0.001f - a, 0.0f);
    return __logf(fmaxf(a, 0.001f));
}
__device__ __forceinline__ float op_exp(float a, float& r) {
    r += fmaxf(-10.0f - a, 0.0f) + fmaxf(a - 4.0f, 0.0f);
    return __expf(fminf(fmaxf(a, -10.0f), 4.0f));
}
__device__ __forceinline__ u64 opk_mul(u64 A, u64 B, float& r) {
    float2 a = unpk(A), b = unpk(B);
    return pk(op_mul(a.x, b.x, r), op_mul(a.y, b.y, r));
}
__device__ __forceinline__ u64 opk_div(u64 A, u64 B, float& r) {
    float2 a = unpk(A), b = unpk(B);
    return pk(op_div(a.x, b.x, r), op_div(a.y, b.y, r));
}
__device__ __forceinline__ u64 opk_log(u64 A, float& r) {
    float2 a = unpk(A); return pk(op_log(a.x, r), op_log(a.y, r));
}
__device__ __forceinline__ u64 opk_exp(u64 A, float& r) {
    float2 a = unpk(A); return pk(op_exp(a.x, r), op_exp(a.y, r));
}
__device__ __forceinline__ u64 opk_sin(u64 A) {
    float2 a = unpk(A); return pk(__sinf(a.x), __sinf(a.y));
}
__device__ __forceinline__ u64 opk_cos(u64 A) {
    float2 a = unpk(A); return pk(__cosf(a.x), __cosf(a.y));
}

// smem: per-dim joint weight rows (dup'd): swd[d][44] u64 (41 used, pad 16B)
#define WD_STRIDE 44
// tail weights (dup'd): L1@0(18) L2@18(48) L3@66(112) L4@178(132) L5@310(156)
// head@466(30) -> 496 u64
#define TWD_U64   496

// ---------------- phase 2: fused single-pass network ----------------
__global__ void __launch_bounds__(NTHR, 4)
eql_main(const float* __restrict__ constb, float* __restrict__ out) {
    __shared__ __align__(16) u64 swd[64 * WD_STRIDE];   // 22528 B
    __shared__ __align__(16) u64 stwd[TWD_U64];         // 3968 B
    __shared__ float sbias[44];
    __shared__ float sred[4];

    const int t  = threadIdx.x;
    const int bt = blockIdx.x;
    const int o  = blockIdx.y;
    const int s  = blockIdx.z;
    const int so = s * O_NUM + o;
    const int pg = bt * NTHR + t;      // global batch-pair index [0, 2048)

    const float* wg = g_constw + (size_t)so * WSHAPE;

    // stage per-dim joint obs-weight rows (dup'd into both f32x2 lanes)
    for (int idx = t; idx < 64 * WD_STRIDE; idx += NTHR) {
        int d = idx / WD_STRIDE, ej = idx % WD_STRIDE;
        float w = 0.0f;
        if (ej < E_JOINT) w = wg[EJ_WG[ej] + d * EJ_IN[ej] + EJ_EB[ej]];
        swd[idx] = dup2(w);
    }
    // stage tail weights (rows 64.. of each layer), dup'd
    {
        const int SEG_WG[6] = {384, 786, 1346, 1970, 2486, 3026};
        const int SEG_IN[6] = {6, 8, 8, 6, 6, 1};
        const int SEG_NR[6] = {3, 6, 14, 22, 26, 30};
        const int SEG_TB[6] = {0, 18, 66, 178, 310, 466};
        #pragma unroll
        for (int sg = 0; sg < 6; sg++) {
            int n = SEG_IN[sg] * SEG_NR[sg];
            for (int i = t; i < n; i += NTHR)
                stwd[SEG_TB[sg] + i] = dup2(wg[SEG_WG[sg] + 64 * SEG_IN[sg] + i]);
        }
    }
    if (t < BSHAPE) sbias[t] = constb[o * BSHAPE + t];
    __syncthreads();

    // ---- single pass over 64 obs dims into 41 packed accumulators ----
    u64 acc[E_JOINT];
    #pragma unroll
    for (int ej = 0; ej < E_JOINT; ej++) acc[ej] = dup2(sbias[ej]);

    const u64* obsT64 = reinterpret_cast<const u64*>(g_obsT);
    #pragma unroll 2
    for (int d = 0; d < 64; d++) {
        u64 ov = obsT64[d * NPAIR + pg];           // coalesced LDG.64 (L1/L2)
        const ulonglong2* wrow =
            reinterpret_cast<const ulonglong2*>(swd + d * WD_STRIDE);
        #pragma unroll
        for (int k2 = 0; k2 < 20; k2++) {          // 40 weights: LDS.128 x20
            ulonglong2 w = wrow[k2];
            acc[2 * k2]     = ffma2(ov, w.x, acc[2 * k2]);
            acc[2 * k2 + 1] = ffma2(ov, w.y, acc[2 * k2 + 1]);
        }
        acc[40] = ffma2(ov, swd[d * WD_STRIDE + 40], acc[40]);
    }

    // ---- nonlinear tail (register-resident, same ordering as reference) ----
    u64 h[30];
    u64 ta[8];
    float racc = 0.0f;

    // L0: ej 0-5, mul x3
    h[0] = opk_mul(acc[0], acc[1], racc);
    h[1] = opk_mul(acc[2], acc[3], racc);
    h[2] = opk_mul(acc[4], acc[5], racc);

    // L1: ej 6-11 + tail(3 x 6), div x3
    #pragma unroll
    for (int e = 0; e < 6; e++) ta[e] = acc[6 + e];
    #pragma unroll
    for (int r = 0; r < 3; r++) {
        const u64* w = stwd + 0 + r * 6;
        #pragma unroll
        for (int e = 0; e < 6; e++) ta[e] = ffma2(h[r], w[e], ta[e]);
    }
    h[3] = opk_div(ta[0], ta[1], racc);
    h[4] = opk_div(ta[2], ta[3], racc);
    h[5] = opk_div(ta[4], ta[5], racc);

    // L2: ej 12-19 + tail(6 x 8), log,log,exp,exp,sin,sin,cos,cos
    #pragma unroll
    for (int e = 0; e < 8; e++) ta[e] = acc[12 + e];
    #pragma unroll
    for (int r = 0; r < 6; r++) {
        const u64* w = stwd + 18 + r * 8;
        #pragma unroll
        for (int e = 0; e < 8; e++) ta[e] = ffma2(h[r], w[e], ta[e]);
    }
    h[6]  = opk_log(ta[0], racc);
    h[7]  = opk_log(ta[1], racc);
    h[8]  = opk_exp(ta[2], racc);
    h[9]  = opk_exp(ta[3], racc);
    h[10] = opk_sin(ta[4]);
    h[11] = opk_sin(ta[5]);
    h[12] = opk_cos(ta[6]);
    h[13] = opk_cos(ta[7]);

    // L3: ej 20-27 + tail(14 x 8)
    #pragma unroll
    for (int e = 0; e < 8; e++) ta[e] = acc[20 + e];
    #pragma unroll
    for (int r = 0; r < 14; r++) {
        const u64* w = stwd + 66 + r * 8;
        #pragma unroll
        for (int e = 0; e < 8; e++) ta[e] = ffma2(h[r], w[e], ta[e]);
    }
    h[14] = opk_log(ta[0], racc);
    h[15] = opk_log(ta[1], racc);
    h[16] = opk_exp(ta[2], racc);
    h[17] = opk_exp(ta[3], racc);
    h[18] = opk_sin(ta[4]);
    h[19] = opk_sin(ta[5]);
    h[20] = opk_cos(ta[6]);
    h[21] = opk_cos(ta[7]);

    // L4: ej 28-33 + tail(22 x 6), mul,div,log,exp
    #pragma unroll
    for (int e = 0; e < 6; e++) ta[e] = acc[28 + e];
    #pragma unroll
    for (int r = 0; r < 22; r++) {
        const u64* w = stwd + 178 + r * 6;
        #pragma unroll
        for (int e = 0; e < 6; e++) ta[e] = ffma2(h[r], w[e], ta[e]);
    }
    h[22] = opk_mul(ta[0], ta[1], racc);
    h[23] = opk_div(ta[2], ta[3], racc);
    h[24] = opk_log(ta[4], racc);
    h[25] = opk_exp(ta[5], racc);

    // L5: ej 34-39 + tail(26 x 6)
    #pragma unroll
    for (int e = 0; e < 6; e++) ta[e] = acc[34 + e];
    #pragma unroll
    for (int r = 0; r < 26; r++) {
        const u64* w = stwd + 310 + r * 6;
        #pragma unroll
        for (int e = 0; e < 6; e++) ta[e] = ffma2(h[r], w[e], ta[e]);
    }
    h[26] = opk_mul(ta[0], ta[1], racc);
    h[27] = opk_div(ta[2], ta[3], racc);
    h[28] = opk_log(ta[4], racc);
    h[29] = opk_exp(ta[5], racc);

    // head: ej 40 + tail(30 x 1)
    u64 last = acc[40];
    #pragma unroll
    for (int r = 0; r < 30; r++) last = ffma2(h[r], stwd[466 + r], last);

    float2 lv = unpk(last);
    const int b = 2 * pg;
    out[((size_t)(s * BATCH + b))     * O_NUM + o] = lv.x;
    out[((size_t)(s * BATCH + b + 1)) * O_NUM + o] = lv.y;

    // regu block reduction (deterministic)
    #pragma unroll
    for (int off = 16; off > 0; off >>= 1)
        racc += __shfl_down_sync(0xFFFFFFFFu, racc, off);
    if ((t & 31) == 0) sred[t >> 5] = racc;
    __syncthreads();
    if (t == 0) {
        float p = (sred[0] + sred[1]) + (sred[2] + sred[3]);
        g_partials[so * NBLK_B + bt] = p;
    }
}

// ---------------- phase 3: regu final reduce ----------------
__global__ void eql_reduce(float* __restrict__ out) {
    __shared__ double sd[256];
    double acc = 0.0;
    for (int i = threadIdx.x; i < NPART; i += 256) acc += (double)g_partials[i];
    sd[threadIdx.x] = acc;
    __syncthreads();
    for (int k = 128; k > 0; k >>= 1) {
        if (threadIdx.x < k) sd[threadIdx.x] += sd[threadIdx.x + k];
        __syncthreads();
    }
    if (threadIdx.x == 0)
        out[TOTAL_ELEMS] = (float)(sd[0] / (double)TOTAL_ELEMS);
}

// ---------------- launch ----------------
extern "C" void kernel_launch(void* const* d_in, const int* in_sizes, int n_in,
                              void* d_out, int out_size) {
    const float* obs    = (const float*)d_in[0];   // (4096, 64)
    const float* scores = (const float*)d_in[1];   // (15, 3120)
    const float* cwbase = (const float*)d_in[2];   // (15, 3120)
    const float* constb = (const float*)d_in[3];   // (15, 41)
    const float* u0     = (const float*)d_in[4];   // (16, 15, 3120)
    const float* u1     = (const float*)d_in[5];   // (16, 15, 3120)
    float* out = (float*)d_out;                    // 983040 outs + 1 regu

    int ntot = SO_NUM * WSHAPE;                    // 748800
    // launch slotting: eql_main must be launch #4 (ncu capture window)
    eql_constw<<<(ntot + 255) / 256, 256>>>(scores, cwbase, u0, u1);   // #1
    {
        dim3 gT(BATCH / 32, N_IN / 32);            // (128, 2)
        dim3 bT(32, 8);
        eql_transpose<<<gT, bT>>>(obs);                                 // #2
    }
    eql_zero<<<(NPART + 255) / 256, 256>>>();                           // #3

    dim3 grid(NBLK_B, O_NUM, S_NUM);               // (16, 15, 16)
    eql_main<<<grid, NTHR>>>(constb, out);                              // #4

    eql_reduce<<<1, 256>>>(out);                                        // #5
}